// round 1
// baseline (speedup 1.0000x reference)
#include <cuda_runtime.h>
#include <cstdint>

// Problem constants
#define NN   32
#define CC   64
#define HH   112
#define WW   112
#define HW   (HH*WW)        // 12544
#define OO   64
#define TAPS 9

// Scratch (static device globals — no allocation)
__device__ unsigned long long g_packed[NN * HW];   // 3.2 MB, bit c = (A[n][c][y][x] > 0)
__device__ unsigned long long g_wbits[OO * TAPS];  // bit c = (W[o][c][tap] > 0)
__device__ int                g_popcw[OO * TAPS];  // popcount of g_wbits

// ---------------------------------------------------------------------------
// Kernel 1: pack weights. weights layout: [o][c][kh][kw] flattened (o*64+c)*9+tap
// ---------------------------------------------------------------------------
__global__ void pack_weights_kernel(const float* __restrict__ w) {
    int i = threadIdx.x;
    if (i >= OO * TAPS) return;
    int o = i / TAPS, t = i % TAPS;
    unsigned long long bits = 0ull;
#pragma unroll
    for (int c = 0; c < CC; c++) {
        float v = w[(o * CC + c) * TAPS + t];
        bits |= (unsigned long long)(v > 0.0f) << c;
    }
    g_wbits[i] = bits;
    g_popcw[i] = __popcll(bits);
}

// ---------------------------------------------------------------------------
// Kernel 2: pack activations. One warp packs 32 consecutive pixels of one n.
// Lane = pixel; loop c: coalesced 128B loads per iteration; build bits in regs.
// HW (12544) is divisible by 32 so a warp never crosses an n boundary.
// ---------------------------------------------------------------------------
__global__ void pack_act_kernel(const float* __restrict__ act) {
    int wid  = blockIdx.x * (blockDim.x >> 5) + (threadIdx.x >> 5);
    int lane = threadIdx.x & 31;
    int p0   = wid * 32;                 // global pixel index base (n*HW + p)
    int n    = p0 / HW;
    int p    = p0 - n * HW;

    const float* base = act + (long)(n * CC) * HW + p + lane;
    unsigned long long word = 0ull;
#pragma unroll
    for (int c = 0; c < CC; c++) {
        float v = __ldg(base + (long)c * HW);
        word |= (unsigned long long)(v > 0.0f) << c;
    }
    g_packed[p0 + lane] = word;
}

// ---------------------------------------------------------------------------
// Kernel 3: binary conv.
// Block = (128, 4): x = threadIdx.x (0..111 used), 4 rows per block.
// grid = (28, 32): blockIdx.x = row group, blockIdx.y = n.
// Each thread: 3x3 packed window in registers, loops all 64 output channels.
// Weights broadcast from shared memory.
// out[pixel][o] = 64*nvalid - 2*sum_popc(a^w) + 2*sum_{invalid taps} popc(w)
// ---------------------------------------------------------------------------
__global__ __launch_bounds__(512, 2)
void bconv_kernel(float* __restrict__ out) {
    __shared__ unsigned long long ws[OO * TAPS];
    __shared__ int                pw[OO * TAPS];

    int t = threadIdx.y * blockDim.x + threadIdx.x;
    for (int i = t; i < OO * TAPS; i += 512) {
        ws[i] = g_wbits[i];
        pw[i] = g_popcw[i];
    }
    __syncthreads();

    int x = threadIdx.x;
    if (x >= WW) return;
    int y = blockIdx.x * 4 + threadIdx.y;
    int n = blockIdx.y;

    const unsigned long long* pb = g_packed + (long)n * HW;

    // Load 3x3 window of packed activations; OOB -> 0 bits, tracked in imask.
    unsigned long long a[9];
    unsigned imask = 0;
#pragma unroll
    for (int tt = 0; tt < 9; tt++) {
        int dy = tt / 3 - 1, dx = tt % 3 - 1;
        int yy = y + dy, xx = x + dx;
        bool v = ((unsigned)yy < (unsigned)HH) && ((unsigned)xx < (unsigned)WW);
        a[tt] = v ? __ldg(pb + yy * WW + xx) : 0ull;
        if (!v) imask |= 1u << tt;
    }

    int nvalid = 9 - __popc(imask);
    int base   = CC * nvalid;

    float* ob = out + (long)(n * OO) * HW + y * WW + x;

#pragma unroll 4
    for (int o = 0; o < OO; o++) {
        int acc = 0;
#pragma unroll
        for (int tt = 0; tt < 9; tt++) {
            acc += __popcll(a[tt] ^ ws[o * TAPS + tt]);
        }
        int res = base - 2 * acc;
        if (imask) {
            int corr = 0;
#pragma unroll
            for (int tt = 0; tt < 9; tt++)
                if ((imask >> tt) & 1) corr += pw[o * TAPS + tt];
            res += 2 * corr;
        }
        ob[(long)o * HW] = (float)res;
    }
}

// ---------------------------------------------------------------------------
// Launch
// ---------------------------------------------------------------------------
extern "C" void kernel_launch(void* const* d_in, const int* in_sizes, int n_in,
                              void* d_out, int out_size) {
    const float* act = (const float*)d_in[0];   // [32,64,112,112]
    const float* w   = (const float*)d_in[1];   // [64*64*9, 1]
    float* out       = (float*)d_out;           // [32,64,112,112]

    pack_weights_kernel<<<1, OO * TAPS>>>(w);

    // 32*12544/32 = 12544 warps; 8 warps/block -> 1568 blocks
    pack_act_kernel<<<(NN * HW) / (32 * 8), 256>>>(act);

    dim3 block(128, 4);
    dim3 grid(HH / 4, NN);
    bconv_kernel<<<grid, block>>>(out);
}